// round 1
// baseline (speedup 1.0000x reference)
#include <cuda_runtime.h>
#include <cstdint>

#define N_NODES  4096
#define IN_FEAT  256
#define N_HEADS  8
#define N_HIDDEN 32
#define OUT_FEAT 256   // N_HEADS * N_HIDDEN

// ---------------- device scratch (no allocations allowed) ----------------
__device__ float g_buf[N_NODES * OUT_FEAT];          // g = h @ W^T   (4 MB)
__device__ float SIAg[N_NODES * N_HEADS];            // exp(s_i)
__device__ float SIBg[N_NODES * N_HEADS];            // exp(0.2*s_i)
__device__ float SJAg[N_NODES * N_HEADS];            // exp(s_j)
__device__ float SJBg[N_NODES * N_HEADS];            // exp(0.2*s_j)

// ---------------- K1: g = h @ W^T  (both row-major, K contiguous) --------
__global__ __launch_bounds__(256) void gemm_g_kernel(const float* __restrict__ A,
                                                     const float* __restrict__ W) {
    __shared__ float As[16][68];
    __shared__ float Bs[16][68];
    const int tid = threadIdx.x;
    const int n0 = blockIdx.x * 64;
    const int m0 = blockIdx.y * 64;
    const int tx = tid & 15, ty = tid >> 4;

    float c[4][4];
#pragma unroll
    for (int i = 0; i < 4; i++)
#pragma unroll
        for (int j = 0; j < 4; j++) c[i][j] = 0.f;

    const int r  = tid >> 2;          // 0..63
    const int kq = (tid & 3) << 2;    // 0,4,8,12

    for (int k0 = 0; k0 < IN_FEAT; k0 += 16) {
        float4 av = *(const float4*)(A + (n0 + r) * IN_FEAT + k0 + kq);
        float4 bv = *(const float4*)(W + (m0 + r) * IN_FEAT + k0 + kq);
        As[kq + 0][r] = av.x; As[kq + 1][r] = av.y; As[kq + 2][r] = av.z; As[kq + 3][r] = av.w;
        Bs[kq + 0][r] = bv.x; Bs[kq + 1][r] = bv.y; Bs[kq + 2][r] = bv.z; Bs[kq + 3][r] = bv.w;
        __syncthreads();
#pragma unroll
        for (int k = 0; k < 16; k++) {
            float4 a4 = *(const float4*)&As[k][ty * 4];
            float4 b4 = *(const float4*)&Bs[k][tx * 4];
            float aa[4] = {a4.x, a4.y, a4.z, a4.w};
            float bb[4] = {b4.x, b4.y, b4.z, b4.w};
#pragma unroll
            for (int i = 0; i < 4; i++)
#pragma unroll
                for (int j = 0; j < 4; j++) c[i][j] = fmaf(aa[i], bb[j], c[i][j]);
        }
        __syncthreads();
    }
#pragma unroll
    for (int i = 0; i < 4; i++) {
        float4 o = make_float4(c[i][0], c[i][1], c[i][2], c[i][3]);
        *(float4*)(g_buf + (n0 + ty * 4 + i) * OUT_FEAT + m0 + tx * 4) = o;
    }
}

// ---------------- K2: per-node scores + factored exps --------------------
__global__ __launch_bounds__(256) void s_kernel(const float* __restrict__ a) {
    __shared__ float a_s[64];
    const int tid = threadIdx.x;
    if (tid < 64) a_s[tid] = a[tid];
    __syncthreads();
    const int idx = blockIdx.x * 256 + tid;   // (n, h) pair: 0..32767
    const int n = idx >> 3, h = idx & 7;
    const float* grow = g_buf + n * OUT_FEAT + h * N_HIDDEN;
    float si = 0.f, sj = 0.f;
#pragma unroll
    for (int f = 0; f < N_HIDDEN; f++) {
        float gv = grow[f];
        si = fmaf(gv, a_s[f], si);
        sj = fmaf(gv, a_s[32 + f], sj);
    }
    SIAg[idx] = expf(si);        SIBg[idx] = expf(0.2f * si);
    SJAg[idx] = expf(sj);        SJBg[idx] = expf(0.2f * sj);
}

// ---------------- K3: fused masked-softmax attention ---------------------
// Block: 256 threads handles 32 i-rows, loops over 128 j-tiles of 32.
// Weight identity: exp(leaky_relu(si+sj)) == max(e^si * e^sj, e^.2si * e^.2sj)
//
// smem layout (dynamic, 105600 B):
//   g_s    [32][256] f32            @ 0       (32 KB)
//   w2_s   [32jj][8h][32i] f32x2    @ 32768   (64 KB)  (w duplicated in both halves)
//   adj_s  [32jj][33] int           @ 98304   (4224 B, padded -> conflict-free)
//   sjA_s  [32][8] f32              @ 102528
//   sjB_s  [32][8] f32              @ 103552
//   rden_s [32][8] f32              @ 104576
#define SMEM_ATTN 105600

__global__ __launch_bounds__(256) void attn_kernel(const int* __restrict__ adj,
                                                   float* __restrict__ out) {
    extern __shared__ unsigned char smem[];
    float*              g_s    = (float*)(smem);
    unsigned long long* w2_s   = (unsigned long long*)(smem + 32768);
    int*                adj_s  = (int*)(smem + 98304);
    float*              sjA_s  = (float*)(smem + 102528);
    float*              sjB_s  = (float*)(smem + 103552);
    float*              rden_s = (float*)(smem + 104576);

    const int tid = threadIdx.x;
    const int i0  = blockIdx.x * 32;

    // phase-A identity: one (i-local, head) pair per thread
    const int ia = tid & 31, ha = tid >> 5;
    const float siA_r = SIAg[(i0 + ia) * 8 + ha];
    const float siB_r = SIBg[(i0 + ia) * 8 + ha];
    float den = 0.f;

    // phase-B identity: warp == head; lane -> (fi: f-quad, ii: i-oct)
    const int h = tid >> 5;
    const int lane = tid & 31;
    const int fi = lane & 7, ii = lane >> 3;

    unsigned long long acc[16];           // 8 i-rows x 2 f32x2 pairs (f = fi*4..fi*4+3)
#pragma unroll
    for (int q = 0; q < 16; q++) acc[q] = 0ull;

    const int adj_r = tid >> 3, adj_q = tid & 7;
    const long long adj_row_off = (long long)(i0 + adj_r) * N_NODES;

    for (int t = 0; t < N_NODES / 32; t++) {
        const int j0 = t * 32;

        // ---- stage tiles ----
        const float4* gsrc = (const float4*)(g_buf + j0 * OUT_FEAT);
        float4* gdst = (float4*)g_s;
#pragma unroll
        for (int q = 0; q < 8; q++) gdst[tid + 256 * q] = gsrc[tid + 256 * q];

        int4 av = *(const int4*)(adj + adj_row_off + j0 + adj_q * 4);
        adj_s[(adj_q * 4 + 0) * 33 + adj_r] = av.x;
        adj_s[(adj_q * 4 + 1) * 33 + adj_r] = av.y;
        adj_s[(adj_q * 4 + 2) * 33 + adj_r] = av.z;
        adj_s[(adj_q * 4 + 3) * 33 + adj_r] = av.w;

        sjA_s[tid] = SJAg[j0 * 8 + tid];
        sjB_s[tid] = SJBg[j0 * 8 + tid];
        __syncthreads();

        // ---- phase A: masked softmax numerators -> smem (pre-duplicated f32x2) ----
#pragma unroll 8
        for (int jj = 0; jj < 32; jj++) {
            float wA = siA_r * sjA_s[jj * 8 + ha];
            float wB = siB_r * sjB_s[jj * 8 + ha];
            float w  = fmaxf(wA, wB);                    // == exp(leaky_relu(si+sj))
            w = (adj_s[jj * 33 + ia] != 0) ? w : 0.f;    // mask
            den += w;
            unsigned long long w2;
            asm("mov.b64 %0, {%1, %1};" : "=l"(w2) : "f"(w));
            w2_s[(jj * 8 + ha) * 32 + ia] = w2;
        }
        __syncthreads();

        // ---- phase B: acc[i][f] += w * g[j][f]  via fma.rn.f32x2 ----
#pragma unroll 4
        for (int jj = 0; jj < 32; jj++) {
            ulonglong2 gp = ((const ulonglong2*)g_s)[jj * 64 + h * 8 + fi]; // 4 f values
            const ulonglong2* wrow = (const ulonglong2*)(w2_s + (jj * 8 + h) * 32 + ii * 8);
#pragma unroll
            for (int k2 = 0; k2 < 4; k2++) {
                ulonglong2 wv = wrow[k2];   // i = ii*8 + 2k2 (wv.x), +1 (wv.y)
                asm("fma.rn.f32x2 %0, %1, %2, %0;" : "+l"(acc[(k2 * 2 + 0) * 2 + 0]) : "l"(wv.x), "l"(gp.x));
                asm("fma.rn.f32x2 %0, %1, %2, %0;" : "+l"(acc[(k2 * 2 + 0) * 2 + 1]) : "l"(wv.x), "l"(gp.y));
                asm("fma.rn.f32x2 %0, %1, %2, %0;" : "+l"(acc[(k2 * 2 + 1) * 2 + 0]) : "l"(wv.y), "l"(gp.x));
                asm("fma.rn.f32x2 %0, %1, %2, %0;" : "+l"(acc[(k2 * 2 + 1) * 2 + 1]) : "l"(wv.y), "l"(gp.y));
            }
        }
        __syncthreads();
    }

    // ---- normalize + write ----
    rden_s[ia * 8 + ha] = 1.0f / den;
    __syncthreads();

#pragma unroll
    for (int io = 0; io < 8; io++) {
        int i = ii * 8 + io;
        float rd = rden_s[i * 8 + h];
        unsigned long long rd2;
        asm("mov.b64 %0, {%1, %1};" : "=l"(rd2) : "f"(rd));
        ulonglong2 o;
        asm("mul.rn.f32x2 %0, %1, %2;" : "=l"(o.x) : "l"(acc[io * 2 + 0]), "l"(rd2));
        asm("mul.rn.f32x2 %0, %1, %2;" : "=l"(o.y) : "l"(acc[io * 2 + 1]), "l"(rd2));
        *(ulonglong2*)(out + (long long)(i0 + i) * OUT_FEAT + h * 32 + fi * 4) = o;
    }
}

// ---------------- launch ----------------
extern "C" void kernel_launch(void* const* d_in, const int* in_sizes, int n_in,
                              void* d_out, int out_size) {
    const float* h = nullptr;
    const float* W = nullptr;
    const float* a = nullptr;
    const int*   adj = nullptr;
    for (int i = 0; i < n_in; i++) {
        switch (in_sizes[i]) {
            case N_NODES * IN_FEAT:    h   = (const float*)d_in[i]; break;  // 1048576
            case OUT_FEAT * IN_FEAT:   W   = (const float*)d_in[i]; break;  // 65536
            case 2 * N_HIDDEN:         a   = (const float*)d_in[i]; break;  // 64
            default:                   adj = (const int*)d_in[i];   break;  // 16777216
        }
    }
    float* out = (float*)d_out;

    cudaFuncSetAttribute(attn_kernel, cudaFuncAttributeMaxDynamicSharedMemorySize, SMEM_ATTN);

    gemm_g_kernel<<<dim3(N_NODES / 64, OUT_FEAT / 64), 256>>>(h, W);
    s_kernel<<<N_NODES * N_HEADS / 256, 256>>>(a);
    attn_kernel<<<N_NODES / 32, 256, SMEM_ATTN>>>(adj, out);
    (void)out_size;
}

// round 2
// speedup vs baseline: 1.9775x; 1.9775x over previous
#include <cuda_runtime.h>
#include <cstdint>

#define N_NODES  4096
#define IN_FEAT  256
#define N_HEADS  8
#define N_HIDDEN 32
#define OUT_FEAT 256   // N_HEADS * N_HIDDEN
#define NSPLIT   4
#define J_PER_SPLIT (N_NODES / NSPLIT)   // 1024

// ---------------- device scratch (no allocations allowed) ----------------
__device__ float g_buf[N_NODES * OUT_FEAT];          // g = h @ W^T   (4 MB)
__device__ float SIAg[N_NODES * N_HEADS];            // exp(s_i)
__device__ float SIBg[N_NODES * N_HEADS];            // exp(0.2*s_i)
__device__ float SJAg[N_NODES * N_HEADS];            // exp(s_j)
__device__ float SJBg[N_NODES * N_HEADS];            // exp(0.2*s_j)
__device__ float num_part[NSPLIT][N_NODES * OUT_FEAT];   // 16 MB partial numerators
__device__ float den_part[NSPLIT][N_NODES * N_HEADS];    // partial denominators

// ---------------- K1: g = h @ W^T  (both row-major, K contiguous) --------
__global__ __launch_bounds__(256) void gemm_g_kernel(const float* __restrict__ A,
                                                     const float* __restrict__ W) {
    __shared__ float As[16][68];
    __shared__ float Bs[16][68];
    const int tid = threadIdx.x;
    const int n0 = blockIdx.x * 64;
    const int m0 = blockIdx.y * 64;
    const int tx = tid & 15, ty = tid >> 4;

    float c[4][4];
#pragma unroll
    for (int i = 0; i < 4; i++)
#pragma unroll
        for (int j = 0; j < 4; j++) c[i][j] = 0.f;

    const int r  = tid >> 2;          // 0..63
    const int kq = (tid & 3) << 2;    // 0,4,8,12

    for (int k0 = 0; k0 < IN_FEAT; k0 += 16) {
        float4 av = *(const float4*)(A + (n0 + r) * IN_FEAT + k0 + kq);
        float4 bv = *(const float4*)(W + (m0 + r) * IN_FEAT + k0 + kq);
        As[kq + 0][r] = av.x; As[kq + 1][r] = av.y; As[kq + 2][r] = av.z; As[kq + 3][r] = av.w;
        Bs[kq + 0][r] = bv.x; Bs[kq + 1][r] = bv.y; Bs[kq + 2][r] = bv.z; Bs[kq + 3][r] = bv.w;
        __syncthreads();
#pragma unroll
        for (int k = 0; k < 16; k++) {
            float4 a4 = *(const float4*)&As[k][ty * 4];
            float4 b4 = *(const float4*)&Bs[k][tx * 4];
            float aa[4] = {a4.x, a4.y, a4.z, a4.w};
            float bb[4] = {b4.x, b4.y, b4.z, b4.w};
#pragma unroll
            for (int i = 0; i < 4; i++)
#pragma unroll
                for (int j = 0; j < 4; j++) c[i][j] = fmaf(aa[i], bb[j], c[i][j]);
        }
        __syncthreads();
    }
#pragma unroll
    for (int i = 0; i < 4; i++) {
        float4 o = make_float4(c[i][0], c[i][1], c[i][2], c[i][3]);
        *(float4*)(g_buf + (n0 + ty * 4 + i) * OUT_FEAT + m0 + tx * 4) = o;
    }
}

// ---------------- K2: per-node scores + factored exps --------------------
__global__ __launch_bounds__(256) void s_kernel(const float* __restrict__ a) {
    __shared__ float a_s[64];
    const int tid = threadIdx.x;
    if (tid < 64) a_s[tid] = a[tid];
    __syncthreads();
    const int idx = blockIdx.x * 256 + tid;   // (n, h) pair: 0..32767
    const int n = idx >> 3, h = idx & 7;
    const float* grow = g_buf + n * OUT_FEAT + h * N_HIDDEN;
    float si = 0.f, sj = 0.f;
#pragma unroll
    for (int f = 0; f < N_HIDDEN; f++) {
        float gv = grow[f];
        si = fmaf(gv, a_s[f], si);
        sj = fmaf(gv, a_s[32 + f], sj);
    }
    SIAg[idx] = expf(si);        SIBg[idx] = expf(0.2f * si);
    SJAg[idx] = expf(sj);        SJBg[idx] = expf(0.2f * sj);
}

// ---------------- K3: fused masked-softmax attention (split-j partials) --
// grid (128 i-blocks, NSPLIT j-splits), 256 threads: 32 i-rows, 32 j-tiles of 32.
// Weight identity: exp(leaky_relu(si+sj)) == max(e^si * e^sj, e^.2si * e^.2sj)
//
// smem layout (dynamic, 105600 B) — 2 CTAs/SM (211 KB <= 228 KB carveout):
//   g_s    [32][256] f32            @ 0       (32 KB)
//   w2_s   [32jj][8h][32i] f32x2    @ 32768   (64 KB)  (w duplicated in both halves)
//   adj_s  [32jj][33] int           @ 98304   (4224 B, padded -> conflict-free)
//   sjA_s  [32][8] f32              @ 102528
//   sjB_s  [32][8] f32              @ 103552
#define SMEM_ATTN 105600

__global__ __launch_bounds__(256, 2) void attn_kernel(const int* __restrict__ adj) {
    extern __shared__ unsigned char smem[];
    float*              g_s    = (float*)(smem);
    unsigned long long* w2_s   = (unsigned long long*)(smem + 32768);
    int*                adj_s  = (int*)(smem + 98304);
    float*              sjA_s  = (float*)(smem + 102528);
    float*              sjB_s  = (float*)(smem + 103552);

    const int tid   = threadIdx.x;
    const int i0    = blockIdx.x * 32;
    const int split = blockIdx.y;
    const int jbase = split * J_PER_SPLIT;

    // phase-A identity: one (i-local, head) pair per thread
    const int ia = tid & 31, ha = tid >> 5;
    const float siA_r = SIAg[(i0 + ia) * 8 + ha];
    const float siB_r = SIBg[(i0 + ia) * 8 + ha];
    float den = 0.f;

    // phase-B identity: warp == head; lane -> (fi: f-quad, ii: i-oct)
    const int h = tid >> 5;
    const int lane = tid & 31;
    const int fi = lane & 7, ii = lane >> 3;

    unsigned long long acc[16];           // 8 i-rows x 2 f32x2 pairs (f = fi*4..fi*4+3)
#pragma unroll
    for (int q = 0; q < 16; q++) acc[q] = 0ull;

    const int adj_r = tid >> 3, adj_q = tid & 7;
    const long long adj_row_off = (long long)(i0 + adj_r) * N_NODES;

    for (int t = 0; t < J_PER_SPLIT / 32; t++) {
        const int j0 = jbase + t * 32;

        // ---- stage tiles ----
        const float4* gsrc = (const float4*)(g_buf + j0 * OUT_FEAT);
        float4* gdst = (float4*)g_s;
#pragma unroll
        for (int q = 0; q < 8; q++) gdst[tid + 256 * q] = gsrc[tid + 256 * q];

        int4 av = *(const int4*)(adj + adj_row_off + j0 + adj_q * 4);
        adj_s[(adj_q * 4 + 0) * 33 + adj_r] = av.x;
        adj_s[(adj_q * 4 + 1) * 33 + adj_r] = av.y;
        adj_s[(adj_q * 4 + 2) * 33 + adj_r] = av.z;
        adj_s[(adj_q * 4 + 3) * 33 + adj_r] = av.w;

        sjA_s[tid] = SJAg[j0 * 8 + tid];
        sjB_s[tid] = SJBg[j0 * 8 + tid];
        __syncthreads();

        // ---- phase A: masked softmax numerators -> smem (pre-duplicated f32x2) ----
#pragma unroll 8
        for (int jj = 0; jj < 32; jj++) {
            float wA = siA_r * sjA_s[jj * 8 + ha];
            float wB = siB_r * sjB_s[jj * 8 + ha];
            float w  = fmaxf(wA, wB);                    // == exp(leaky_relu(si+sj))
            w = (adj_s[jj * 33 + ia] != 0) ? w : 0.f;    // mask
            den += w;
            unsigned long long w2;
            asm("mov.b64 %0, {%1, %1};" : "=l"(w2) : "f"(w));
            w2_s[(jj * 8 + ha) * 32 + ia] = w2;
        }
        __syncthreads();

        // ---- phase B: acc[i][f] += w * g[j][f]  via fma.rn.f32x2 ----
#pragma unroll 4
        for (int jj = 0; jj < 32; jj++) {
            ulonglong2 gp = ((const ulonglong2*)g_s)[jj * 64 + h * 8 + fi]; // 4 f values
            const ulonglong2* wrow = (const ulonglong2*)(w2_s + (jj * 8 + h) * 32 + ii * 8);
#pragma unroll
            for (int k2 = 0; k2 < 4; k2++) {
                ulonglong2 wv = wrow[k2];   // i = ii*8 + 2k2 (wv.x), +1 (wv.y)
                asm("fma.rn.f32x2 %0, %1, %2, %0;" : "+l"(acc[(k2 * 2 + 0) * 2 + 0]) : "l"(wv.x), "l"(gp.x));
                asm("fma.rn.f32x2 %0, %1, %2, %0;" : "+l"(acc[(k2 * 2 + 0) * 2 + 1]) : "l"(wv.x), "l"(gp.y));
                asm("fma.rn.f32x2 %0, %1, %2, %0;" : "+l"(acc[(k2 * 2 + 1) * 2 + 0]) : "l"(wv.y), "l"(gp.x));
                asm("fma.rn.f32x2 %0, %1, %2, %0;" : "+l"(acc[(k2 * 2 + 1) * 2 + 1]) : "l"(wv.y), "l"(gp.y));
            }
        }
        __syncthreads();
    }

    // ---- write partials ----
    den_part[split][(i0 + ia) * N_HEADS + ha] = den;

    float* nump = num_part[split];
#pragma unroll
    for (int io = 0; io < 8; io++) {
        int i = ii * 8 + io;
        ulonglong2 o;
        o.x = acc[io * 2 + 0];
        o.y = acc[io * 2 + 1];
        *(ulonglong2*)(nump + (long long)(i0 + i) * OUT_FEAT + h * 32 + fi * 4) = o;
    }
}

// ---------------- K4: reduce splits + normalize --------------------------
__global__ __launch_bounds__(256) void reduce_kernel(float* __restrict__ out) {
    const int idx = blockIdx.x * 256 + threadIdx.x;    // (i, c), c = hf column
    const int i = idx >> 8, c = idx & 255;
    const int h = c >> 5;
    float s = 0.f, d = 0.f;
#pragma unroll
    for (int sp = 0; sp < NSPLIT; sp++) {
        s += num_part[sp][i * OUT_FEAT + c];
        d += den_part[sp][i * N_HEADS + h];
    }
    out[idx] = s / d;
}

// ---------------- launch ----------------
extern "C" void kernel_launch(void* const* d_in, const int* in_sizes, int n_in,
                              void* d_out, int out_size) {
    const float* h = nullptr;
    const float* W = nullptr;
    const float* a = nullptr;
    const int*   adj = nullptr;
    for (int i = 0; i < n_in; i++) {
        switch (in_sizes[i]) {
            case N_NODES * IN_FEAT:    h   = (const float*)d_in[i]; break;  // 1048576
            case OUT_FEAT * IN_FEAT:   W   = (const float*)d_in[i]; break;  // 65536
            case 2 * N_HIDDEN:         a   = (const float*)d_in[i]; break;  // 64
            default:                   adj = (const int*)d_in[i];   break;  // 16777216
        }
    }
    float* out = (float*)d_out;

    cudaFuncSetAttribute(attn_kernel, cudaFuncAttributeMaxDynamicSharedMemorySize, SMEM_ATTN);

    gemm_g_kernel<<<dim3(N_NODES / 64, OUT_FEAT / 64), 256>>>(h, W);
    s_kernel<<<N_NODES * N_HEADS / 256, 256>>>(a);
    attn_kernel<<<dim3(N_NODES / 32, NSPLIT), 256, SMEM_ATTN>>>(adj);
    reduce_kernel<<<N_NODES * OUT_FEAT / 256, 256>>>(out);
    (void)out_size;
}

// round 4
// speedup vs baseline: 2.2558x; 1.1408x over previous
#include <cuda_runtime.h>
#include <cstdint>

#define N_NODES  4096
#define IN_FEAT  256
#define N_HEADS  8
#define N_HIDDEN 32
#define OUT_FEAT 256   // N_HEADS * N_HIDDEN
#define NSPLIT   16
#define J_PER_SPLIT (N_NODES / NSPLIT)   // 256  -> 8 j-tiles of 32 per CTA

// ---------------- device scratch (no allocations allowed) ----------------
__device__ float g_buf[N_NODES * OUT_FEAT];              // g = h @ W^T   (4 MB)
__device__ float SIAg[N_NODES * N_HEADS];                // exp(s_i)
__device__ float SIBg[N_NODES * N_HEADS];                // exp(0.2*s_i)
__device__ float SJAg[N_NODES * N_HEADS];                // exp(s_j)
__device__ float SJBg[N_NODES * N_HEADS];                // exp(0.2*s_j)
__device__ float num_part[NSPLIT][N_NODES * OUT_FEAT];   // 64 MB partial numerators
__device__ float den_part[NSPLIT][N_NODES * N_HEADS];    // partial denominators

// ---------------- K0: no-op spacer so ncu (4th launch) captures attn -----
__global__ void spacer_kernel() {}

// ---------------- K1: g = h @ W^T  (both row-major, K contiguous) --------
__global__ __launch_bounds__(256) void gemm_g_kernel(const float* __restrict__ A,
                                                     const float* __restrict__ W) {
    __shared__ float As[16][68];
    __shared__ float Bs[16][68];
    const int tid = threadIdx.x;
    const int n0 = blockIdx.x * 64;
    const int m0 = blockIdx.y * 64;
    const int tx = tid & 15, ty = tid >> 4;

    float c[4][4];
#pragma unroll
    for (int i = 0; i < 4; i++)
#pragma unroll
        for (int j = 0; j < 4; j++) c[i][j] = 0.f;

    const int r  = tid >> 2;          // 0..63
    const int kq = (tid & 3) << 2;    // 0,4,8,12

    for (int k0 = 0; k0 < IN_FEAT; k0 += 16) {
        float4 av = *(const float4*)(A + (n0 + r) * IN_FEAT + k0 + kq);
        float4 bv = *(const float4*)(W + (m0 + r) * IN_FEAT + k0 + kq);
        As[kq + 0][r] = av.x; As[kq + 1][r] = av.y; As[kq + 2][r] = av.z; As[kq + 3][r] = av.w;
        Bs[kq + 0][r] = bv.x; Bs[kq + 1][r] = bv.y; Bs[kq + 2][r] = bv.z; Bs[kq + 3][r] = bv.w;
        __syncthreads();
#pragma unroll
        for (int k = 0; k < 16; k++) {
            float4 a4 = *(const float4*)&As[k][ty * 4];
            float4 b4 = *(const float4*)&Bs[k][tx * 4];
            float aa[4] = {a4.x, a4.y, a4.z, a4.w};
            float bb[4] = {b4.x, b4.y, b4.z, b4.w};
#pragma unroll
            for (int i = 0; i < 4; i++)
#pragma unroll
                for (int j = 0; j < 4; j++) c[i][j] = fmaf(aa[i], bb[j], c[i][j]);
        }
        __syncthreads();
    }
#pragma unroll
    for (int i = 0; i < 4; i++) {
        float4 o = make_float4(c[i][0], c[i][1], c[i][2], c[i][3]);
        *(float4*)(g_buf + (n0 + ty * 4 + i) * OUT_FEAT + m0 + tx * 4) = o;
    }
}

// ---------------- K2: per-node scores + factored exps --------------------
__global__ __launch_bounds__(256) void s_kernel(const float* __restrict__ a) {
    __shared__ float a_s[64];
    const int tid = threadIdx.x;
    if (tid < 64) a_s[tid] = a[tid];
    __syncthreads();
    const int idx = blockIdx.x * 256 + tid;   // (n, h) pair: 0..32767
    const int n = idx >> 3, h = idx & 7;
    const float* grow = g_buf + n * OUT_FEAT + h * N_HIDDEN;
    float si = 0.f, sj = 0.f;
#pragma unroll
    for (int f = 0; f < N_HIDDEN; f++) {
        float gv = grow[f];
        si = fmaf(gv, a_s[f], si);
        sj = fmaf(gv, a_s[32 + f], sj);
    }
    SIAg[idx] = expf(si);        SIBg[idx] = expf(0.2f * si);
    SJAg[idx] = expf(sj);        SJBg[idx] = expf(0.2f * sj);
}

// ---------------- K3: fused masked-softmax attention (split-j partials) --
// grid (128 i-blocks, 16 j-splits) = 2048 CTAs, 256 threads.
// Each CTA: 32 i-rows x 256 j (8 j-tiles of 32), register-prefetch pipeline.
// Weight identity: exp(leaky_relu(si+sj)) == max(e^si * e^sj, e^.2si * e^.2sj)
//
// smem layout (dynamic, 105600 B) — 2 CTAs/SM:
//   g_s    [32][256] f32            @ 0       (32 KB)
//   w2_s   [32jj][8h][32i] f32x2    @ 32768   (64 KB) (w duplicated both halves)
//   adj_s  [32jj][33] int           @ 98304   (4224 B, padded -> conflict-free)
//   sjA_s  [32][8] f32              @ 102528
//   sjB_s  [32][8] f32              @ 103552
#define SMEM_ATTN 105600

__global__ __launch_bounds__(256, 2) void attn_kernel(const int* __restrict__ adj) {
    extern __shared__ unsigned char smem[];
    float*              g_s    = (float*)(smem);
    unsigned long long* w2_s   = (unsigned long long*)(smem + 32768);
    int*                adj_s  = (int*)(smem + 98304);
    float*              sjA_s  = (float*)(smem + 102528);
    float*              sjB_s  = (float*)(smem + 103552);

    const int tid   = threadIdx.x;
    const int i0    = blockIdx.x * 32;
    const int split = blockIdx.y;
    const int jbase = split * J_PER_SPLIT;

    // phase-A identity: one (i-local, head) pair per thread
    const int ia = tid & 31, ha = tid >> 5;
    const float siA_r = SIAg[(i0 + ia) * 8 + ha];
    const float siB_r = SIBg[(i0 + ia) * 8 + ha];
    float den = 0.f;

    // phase-B identity: warp == head; lane -> iq (i-quad), fo (f-oct)
    const int h  = tid >> 5;
    const int lane = tid & 31;
    const int iq = lane >> 2;       // 0..7 : i = iq*4 .. iq*4+3
    const int fo = lane & 3;        // 0..3 : f = fo*8 .. fo*8+7

    unsigned long long acc[16];     // acc[il*4 + p]: i=iq*4+il, f-pair p of 4
#pragma unroll
    for (int q = 0; q < 16; q++) acc[q] = 0ull;

    const int adj_r = tid >> 3, adj_q = tid & 7;
    const long long adj_row_off = (long long)(i0 + adj_r) * N_NODES;

    const int NT = J_PER_SPLIT / 32;   // 8 tiles

    // ---- register prefetch buffers ----
    float4 gpre[8];
    int4   apre;
    float  sjApre, sjBpre;

    {   // preload tile 0
        const int j0 = jbase;
        const float4* gsrc = (const float4*)(g_buf + j0 * OUT_FEAT);
#pragma unroll
        for (int q = 0; q < 8; q++) gpre[q] = gsrc[tid + 256 * q];
        apre   = *(const int4*)(adj + adj_row_off + j0 + adj_q * 4);
        sjApre = SJAg[j0 * 8 + tid];
        sjBpre = SJBg[j0 * 8 + tid];
    }

    for (int t = 0; t < NT; t++) {
        // ---- commit prefetched tile to smem ----
        float4* gdst = (float4*)g_s;
#pragma unroll
        for (int q = 0; q < 8; q++) gdst[tid + 256 * q] = gpre[q];
        adj_s[(adj_q * 4 + 0) * 33 + adj_r] = apre.x;
        adj_s[(adj_q * 4 + 1) * 33 + adj_r] = apre.y;
        adj_s[(adj_q * 4 + 2) * 33 + adj_r] = apre.z;
        adj_s[(adj_q * 4 + 3) * 33 + adj_r] = apre.w;
        sjA_s[tid] = sjApre;
        sjB_s[tid] = sjBpre;
        __syncthreads();

        // ---- issue next tile's loads (latency hidden under phases A+B) ----
        if (t + 1 < NT) {
            const int jn = jbase + (t + 1) * 32;
            const float4* gsrc = (const float4*)(g_buf + jn * OUT_FEAT);
#pragma unroll
            for (int q = 0; q < 8; q++) gpre[q] = gsrc[tid + 256 * q];
            apre   = *(const int4*)(adj + adj_row_off + jn + adj_q * 4);
            sjApre = SJAg[jn * 8 + tid];
            sjBpre = SJBg[jn * 8 + tid];
        }

        // ---- phase A: masked softmax numerators -> smem (pre-dup f32x2) ----
#pragma unroll 8
        for (int jj = 0; jj < 32; jj++) {
            float wA = siA_r * sjA_s[jj * 8 + ha];
            float wB = siB_r * sjB_s[jj * 8 + ha];
            float w  = fmaxf(wA, wB);                    // == exp(leaky_relu(si+sj))
            w = (adj_s[jj * 33 + ia] != 0) ? w : 0.f;    // mask
            den += w;
            unsigned long long w2;
            asm("mov.b64 %0, {%1, %1};" : "=l"(w2) : "f"(w));
            w2_s[(jj * 8 + ha) * 32 + ia] = w2;
        }
        __syncthreads();

        // ---- phase B: acc[i][f] += w * g[j][f]  via fma.rn.f32x2 ----
#pragma unroll 4
        for (int jj = 0; jj < 32; jj++) {
            // g values f = fo*8 .. fo*8+7  (two 16B loads)
            const ulonglong2* grow2 = (const ulonglong2*)g_s + jj * 64 + h * 8 + fo * 2;
            ulonglong2 gp0 = grow2[0];
            ulonglong2 gp1 = grow2[1];
            // w pairs i = iq*4 .. iq*4+3 (two 16B loads)
            const ulonglong2* wrow = (const ulonglong2*)(w2_s + (jj * 8 + h) * 32 + iq * 4);
            ulonglong2 w01 = wrow[0];
            ulonglong2 w23 = wrow[1];
            unsigned long long wv;
#pragma unroll
            for (int il = 0; il < 4; il++) {
                wv = (il == 0) ? w01.x : (il == 1) ? w01.y : (il == 2) ? w23.x : w23.y;
                asm("fma.rn.f32x2 %0, %1, %2, %0;" : "+l"(acc[il * 4 + 0]) : "l"(wv), "l"(gp0.x));
                asm("fma.rn.f32x2 %0, %1, %2, %0;" : "+l"(acc[il * 4 + 1]) : "l"(wv), "l"(gp0.y));
                asm("fma.rn.f32x2 %0, %1, %2, %0;" : "+l"(acc[il * 4 + 2]) : "l"(wv), "l"(gp1.x));
                asm("fma.rn.f32x2 %0, %1, %2, %0;" : "+l"(acc[il * 4 + 3]) : "l"(wv), "l"(gp1.y));
            }
        }
        __syncthreads();
    }

    // ---- write partials ----
    den_part[split][(i0 + ia) * N_HEADS + ha] = den;

    float* nump = num_part[split];
#pragma unroll
    for (int il = 0; il < 4; il++) {
        const int i = iq * 4 + il;
        ulonglong2 o0, o1;
        o0.x = acc[il * 4 + 0]; o0.y = acc[il * 4 + 1];
        o1.x = acc[il * 4 + 2]; o1.y = acc[il * 4 + 3];
        float* dst = nump + (long long)(i0 + i) * OUT_FEAT + h * 32 + fo * 8;
        *(ulonglong2*)(dst)     = o0;
        *(ulonglong2*)(dst + 4) = o1;
    }
}

// ---------------- K4: reduce splits + normalize --------------------------
__global__ __launch_bounds__(256) void reduce_kernel(float* __restrict__ out) {
    const int idx = blockIdx.x * 256 + threadIdx.x;   // one float4 of output
    const int i  = idx >> 6;
    const int c4 = (idx & 63) * 4;
    const int h  = c4 >> 5;
    float4 s = make_float4(0.f, 0.f, 0.f, 0.f);
    float  d = 0.f;
#pragma unroll
    for (int sp = 0; sp < NSPLIT; sp++) {
        float4 v = *(const float4*)(num_part[sp] + i * OUT_FEAT + c4);
        s.x += v.x; s.y += v.y; s.z += v.z; s.w += v.w;
        d += den_part[sp][i * N_HEADS + h];
    }
    float rd = 1.0f / d;
    s.x *= rd; s.y *= rd; s.z *= rd; s.w *= rd;
    *(float4*)(out + i * OUT_FEAT + c4) = s;
}

// ---------------- launch ----------------
extern "C" void kernel_launch(void* const* d_in, const int* in_sizes, int n_in,
                              void* d_out, int out_size) {
    const float* h = nullptr;
    const float* W = nullptr;
    const float* a = nullptr;
    const int*   adj = nullptr;
    for (int i = 0; i < n_in; i++) {
        switch (in_sizes[i]) {
            case N_NODES * IN_FEAT:    h   = (const float*)d_in[i]; break;  // 1048576
            case OUT_FEAT * IN_FEAT:   W   = (const float*)d_in[i]; break;  // 65536
            case 2 * N_HIDDEN:         a   = (const float*)d_in[i]; break;  // 64
            default:                   adj = (const int*)d_in[i];   break;  // 16777216
        }
    }
    float* out = (float*)d_out;

    cudaFuncSetAttribute(attn_kernel, cudaFuncAttributeMaxDynamicSharedMemorySize, SMEM_ATTN);

    spacer_kernel<<<1, 32>>>();   // shifts attn to 4th launch for ncu capture
    gemm_g_kernel<<<dim3(N_NODES / 64, OUT_FEAT / 64), 256>>>(h, W);
    s_kernel<<<N_NODES * N_HEADS / 256, 256>>>(a);
    attn_kernel<<<dim3(N_NODES / 32, NSPLIT), 256, SMEM_ATTN>>>(adj);
    reduce_kernel<<<N_NODES * OUT_FEAT / 1024, 256>>>(out);
    (void)out_size;
}

// round 5
// speedup vs baseline: 2.6718x; 1.1844x over previous
#include <cuda_runtime.h>
#include <cstdint>

#define N_NODES  4096
#define IN_FEAT  256
#define N_HEADS  8
#define N_HIDDEN 32
#define OUT_FEAT 256   // N_HEADS * N_HIDDEN
#define NSPLIT   16
#define J_PER_SPLIT (N_NODES / NSPLIT)   // 256  -> 8 j-tiles of 32 per CTA

// ---------------- device scratch (no allocations allowed) ----------------
__device__ float g_buf[N_NODES * OUT_FEAT];              // g = h @ W^T   (4 MB)
__device__ float SIAg[N_NODES * N_HEADS];                // exp(s_i)
__device__ float SIBg[N_NODES * N_HEADS];                // exp(0.2*s_i)
__device__ float SJAg[N_NODES * N_HEADS];                // exp(s_j)
__device__ float SJBg[N_NODES * N_HEADS];                // exp(0.2*s_j)
__device__ float num_part[NSPLIT][N_NODES * OUT_FEAT];   // 64 MB partial numerators
__device__ float den_part[NSPLIT][N_NODES * N_HEADS];    // partial denominators

// ---------------- K0: no-op spacer so ncu (4th launch) captures attn -----
__global__ void spacer_kernel() {}

// ---------------- K1: g = h @ W^T  (both row-major, K contiguous) --------
__global__ __launch_bounds__(256) void gemm_g_kernel(const float* __restrict__ A,
                                                     const float* __restrict__ W) {
    __shared__ float As[16][68];
    __shared__ float Bs[16][68];
    const int tid = threadIdx.x;
    const int n0 = blockIdx.x * 64;
    const int m0 = blockIdx.y * 64;
    const int tx = tid & 15, ty = tid >> 4;

    float c[4][4];
#pragma unroll
    for (int i = 0; i < 4; i++)
#pragma unroll
        for (int j = 0; j < 4; j++) c[i][j] = 0.f;

    const int r  = tid >> 2;          // 0..63
    const int kq = (tid & 3) << 2;    // 0,4,8,12

    for (int k0 = 0; k0 < IN_FEAT; k0 += 16) {
        float4 av = *(const float4*)(A + (n0 + r) * IN_FEAT + k0 + kq);
        float4 bv = *(const float4*)(W + (m0 + r) * IN_FEAT + k0 + kq);
        As[kq + 0][r] = av.x; As[kq + 1][r] = av.y; As[kq + 2][r] = av.z; As[kq + 3][r] = av.w;
        Bs[kq + 0][r] = bv.x; Bs[kq + 1][r] = bv.y; Bs[kq + 2][r] = bv.z; Bs[kq + 3][r] = bv.w;
        __syncthreads();
#pragma unroll
        for (int k = 0; k < 16; k++) {
            float4 a4 = *(const float4*)&As[k][ty * 4];
            float4 b4 = *(const float4*)&Bs[k][tx * 4];
            float aa[4] = {a4.x, a4.y, a4.z, a4.w};
            float bb[4] = {b4.x, b4.y, b4.z, b4.w};
#pragma unroll
            for (int i = 0; i < 4; i++)
#pragma unroll
                for (int j = 0; j < 4; j++) c[i][j] = fmaf(aa[i], bb[j], c[i][j]);
        }
        __syncthreads();
    }
#pragma unroll
    for (int i = 0; i < 4; i++) {
        float4 o = make_float4(c[i][0], c[i][1], c[i][2], c[i][3]);
        *(float4*)(g_buf + (n0 + ty * 4 + i) * OUT_FEAT + m0 + tx * 4) = o;
    }
}

// ---------------- K2: per-node scores + factored exps --------------------
__global__ __launch_bounds__(256) void s_kernel(const float* __restrict__ a) {
    __shared__ float a_s[64];
    const int tid = threadIdx.x;
    if (tid < 64) a_s[tid] = a[tid];
    __syncthreads();
    const int idx = blockIdx.x * 256 + tid;   // (n, h) pair: 0..32767
    const int n = idx >> 3, h = idx & 7;
    const float* grow = g_buf + n * OUT_FEAT + h * N_HIDDEN;
    float si = 0.f, sj = 0.f;
#pragma unroll
    for (int f = 0; f < N_HIDDEN; f++) {
        float gv = grow[f];
        si = fmaf(gv, a_s[f], si);
        sj = fmaf(gv, a_s[32 + f], sj);
    }
    SIAg[idx] = expf(si);        SIBg[idx] = expf(0.2f * si);
    SJAg[idx] = expf(sj);        SJBg[idx] = expf(0.2f * sj);
}

// ---------------- K3: fused masked-softmax attention (split-j partials) --
// grid (128 i-blocks, 16 j-splits) = 2048 CTAs, 256 threads.
// Weight identity: exp(leaky_relu(si+sj)) == max(e^si * e^sj, e^.2si * e^.2sj)
// Adjacency carried as 32-bit row masks (built with redux.sync.or at staging).
//
// smem layout (dynamic, 67712 B) — 2 CTAs/SM:
//   g_s    [32jj][256f] f32   @ 0      (32 KB)
//   w_s    [32jj][8h][32i]f32 @ 32768  (32 KB)
//   bm_s   [32i] u32          @ 65536  (128 B)
//   sjAB_s [32jj][8h] float2  @ 65664  (2 KB)
#define SMEM_ATTN 67712

__global__ __launch_bounds__(256, 2) void attn_kernel(const int* __restrict__ adj) {
    extern __shared__ unsigned char smem[];
    float*        g_s    = (float*)(smem);
    float*        w_s    = (float*)(smem + 32768);
    unsigned int* bm_s   = (unsigned int*)(smem + 65536);
    float2*       sjAB_s = (float2*)(smem + 65664);

    const int tid   = threadIdx.x;
    const int i0    = blockIdx.x * 32;
    const int split = blockIdx.y;
    const int jbase = split * J_PER_SPLIT;

    // phase-A identity: one (i-local, head) pair per thread
    const int ia = tid & 31, ha = tid >> 5;
    const float siA_r = SIAg[(i0 + ia) * 8 + ha];
    const float siB_r = SIBg[(i0 + ia) * 8 + ha];
    float den = 0.f;

    // phase-B identity: warp == head; lane -> iq (i-quad), fo (f-oct)
    const int h  = tid >> 5;
    const int lane = tid & 31;
    const int iq = lane >> 2;       // 0..7 : i = iq*4 .. iq*4+3
    const int fo = lane & 3;        // 0..3 : f = fo*8 .. fo*8+7

    unsigned long long acc[16];     // acc[il*4 + p]: i=iq*4+il, f-pair p of 4
#pragma unroll
    for (int q = 0; q < 16; q++) acc[q] = 0ull;

    const int adj_r = tid >> 3, adj_q = tid & 7;
    const unsigned int red_mask = 0xFFu << (lane & 24);   // 8-lane group for redux
    const long long adj_row_off = (long long)(i0 + adj_r) * N_NODES;

    const int NT = J_PER_SPLIT / 32;   // 8 tiles

    // ---- register prefetch buffers ----
    float4 gpre[8];
    int4   apre;
    float  sjApre, sjBpre;

    {   // preload tile 0
        const int j0 = jbase;
        const float4* gsrc = (const float4*)(g_buf + j0 * OUT_FEAT);
#pragma unroll
        for (int q = 0; q < 8; q++) gpre[q] = gsrc[tid + 256 * q];
        apre   = *(const int4*)(adj + adj_row_off + j0 + adj_q * 4);
        sjApre = SJAg[j0 * 8 + tid];
        sjBpre = SJBg[j0 * 8 + tid];
    }

    for (int t = 0; t < NT; t++) {
        // ---- commit prefetched tile to smem ----
        float4* gdst = (float4*)g_s;
#pragma unroll
        for (int q = 0; q < 8; q++) gdst[tid + 256 * q] = gpre[q];

        // adjacency int4 -> 4-bit nibble -> 32-bit row mask via redux over 8 lanes
        {
            unsigned int nib = (apre.x != 0 ? 1u : 0u) | (apre.y != 0 ? 2u : 0u) |
                               (apre.z != 0 ? 4u : 0u) | (apre.w != 0 ? 8u : 0u);
            unsigned int m = __reduce_or_sync(red_mask, nib << (adj_q * 4));
            if (adj_q == 0) bm_s[adj_r] = m;
        }
        sjAB_s[tid] = make_float2(sjApre, sjBpre);
        __syncthreads();

        // ---- issue next tile's loads (latency hidden under phases A+B) ----
        if (t + 1 < NT) {
            const int jn = jbase + (t + 1) * 32;
            const float4* gsrc = (const float4*)(g_buf + jn * OUT_FEAT);
#pragma unroll
            for (int q = 0; q < 8; q++) gpre[q] = gsrc[tid + 256 * q];
            apre   = *(const int4*)(adj + adj_row_off + jn + adj_q * 4);
            sjApre = SJAg[jn * 8 + tid];
            sjBpre = SJBg[jn * 8 + tid];
        }

        // ---- phase A: masked softmax numerators -> smem (plain f32) ----
        const unsigned int mrow = bm_s[ia];   // one 4B LDS per tile
#pragma unroll
        for (int jj = 0; jj < 32; jj++) {
            float2 sj = sjAB_s[jj * 8 + ha];            // 8B broadcast
            float wA = siA_r * sj.x;
            float wB = siB_r * sj.y;
            float w  = fmaxf(wA, wB);                   // == exp(leaky_relu(si+sj))
            w = (mrow & (1u << jj)) ? w : 0.f;          // mask (const bit per jj)
            den += w;
            w_s[(jj * 8 + ha) * 32 + ia] = w;
        }
        __syncthreads();

        // ---- phase B: acc[i][f] += w * g[j][f]  via fma.rn.f32x2 ----
#pragma unroll 4
        for (int jj = 0; jj < 32; jj++) {
            // g values f = fo*8 .. fo*8+7  (two 16B loads, 4-way distinct/warp)
            const ulonglong2* grow2 = (const ulonglong2*)g_s + jj * 64 + h * 8 + fo * 2;
            ulonglong2 gp0 = grow2[0];
            ulonglong2 gp1 = grow2[1];
            // w values i = iq*4..+3 (one 16B load), duplicate to f32x2 in regs
            float4 w4 = *(const float4*)(w_s + (jj * 8 + h) * 32 + iq * 4);
            unsigned long long wd[4];
            asm("mov.b64 %0, {%1, %1};" : "=l"(wd[0]) : "f"(w4.x));
            asm("mov.b64 %0, {%1, %1};" : "=l"(wd[1]) : "f"(w4.y));
            asm("mov.b64 %0, {%1, %1};" : "=l"(wd[2]) : "f"(w4.z));
            asm("mov.b64 %0, {%1, %1};" : "=l"(wd[3]) : "f"(w4.w));
#pragma unroll
            for (int il = 0; il < 4; il++) {
                asm("fma.rn.f32x2 %0, %1, %2, %0;" : "+l"(acc[il * 4 + 0]) : "l"(wd[il]), "l"(gp0.x));
                asm("fma.rn.f32x2 %0, %1, %2, %0;" : "+l"(acc[il * 4 + 1]) : "l"(wd[il]), "l"(gp0.y));
                asm("fma.rn.f32x2 %0, %1, %2, %0;" : "+l"(acc[il * 4 + 2]) : "l"(wd[il]), "l"(gp1.x));
                asm("fma.rn.f32x2 %0, %1, %2, %0;" : "+l"(acc[il * 4 + 3]) : "l"(wd[il]), "l"(gp1.y));
            }
        }
        __syncthreads();
    }

    // ---- write partials ----
    den_part[split][(i0 + ia) * N_HEADS + ha] = den;

    float* nump = num_part[split];
#pragma unroll
    for (int il = 0; il < 4; il++) {
        const int i = iq * 4 + il;
        ulonglong2 o0, o1;
        o0.x = acc[il * 4 + 0]; o0.y = acc[il * 4 + 1];
        o1.x = acc[il * 4 + 2]; o1.y = acc[il * 4 + 3];
        float* dst = nump + (long long)(i0 + i) * OUT_FEAT + h * 32 + fo * 8;
        *(ulonglong2*)(dst)     = o0;
        *(ulonglong2*)(dst + 4) = o1;
    }
}

// ---------------- K4: reduce splits + normalize --------------------------
__global__ __launch_bounds__(256) void reduce_kernel(float* __restrict__ out) {
    const int idx = blockIdx.x * 256 + threadIdx.x;   // one float4 of output
    const int i  = idx >> 6;
    const int c4 = (idx & 63) * 4;
    const int h  = c4 >> 5;
    float4 s = make_float4(0.f, 0.f, 0.f, 0.f);
    float  d = 0.f;
#pragma unroll
    for (int sp = 0; sp < NSPLIT; sp++) {
        float4 v = *(const float4*)(num_part[sp] + i * OUT_FEAT + c4);
        s.x += v.x; s.y += v.y; s.z += v.z; s.w += v.w;
        d += den_part[sp][i * N_HEADS + h];
    }
    float rd = 1.0f / d;
    s.x *= rd; s.y *= rd; s.z *= rd; s.w *= rd;
    *(float4*)(out + i * OUT_FEAT + c4) = s;
}

// ---------------- launch ----------------
extern "C" void kernel_launch(void* const* d_in, const int* in_sizes, int n_in,
                              void* d_out, int out_size) {
    const float* h = nullptr;
    const float* W = nullptr;
    const float* a = nullptr;
    const int*   adj = nullptr;
    for (int i = 0; i < n_in; i++) {
        switch (in_sizes[i]) {
            case N_NODES * IN_FEAT:    h   = (const float*)d_in[i]; break;  // 1048576
            case OUT_FEAT * IN_FEAT:   W   = (const float*)d_in[i]; break;  // 65536
            case 2 * N_HIDDEN:         a   = (const float*)d_in[i]; break;  // 64
            default:                   adj = (const int*)d_in[i];   break;  // 16777216
        }
    }
    float* out = (float*)d_out;

    cudaFuncSetAttribute(attn_kernel, cudaFuncAttributeMaxDynamicSharedMemorySize, SMEM_ATTN);

    spacer_kernel<<<1, 32>>>();   // keeps attn at 4th launch for ncu capture
    gemm_g_kernel<<<dim3(N_NODES / 64, OUT_FEAT / 64), 256>>>(h, W);
    s_kernel<<<N_NODES * N_HEADS / 256, 256>>>(a);
    attn_kernel<<<dim3(N_NODES / 32, NSPLIT), 256, SMEM_ATTN>>>(adj);
    reduce_kernel<<<N_NODES * OUT_FEAT / 1024, 256>>>(out);
    (void)out_size;
}

// round 10
// speedup vs baseline: 2.7229x; 1.0191x over previous
#include <cuda_runtime.h>
#include <cstdint>

#define N_NODES  4096
#define IN_FEAT  256
#define N_HEADS  8
#define N_HIDDEN 32
#define OUT_FEAT 256   // N_HEADS * N_HIDDEN
#define NSPLIT   16
#define J_PER_SPLIT (N_NODES / NSPLIT)   // 256  -> 8 j-tiles of 32 per CTA

// ---------------- device scratch (no allocations allowed) ----------------
__device__ float  g_buf[N_NODES * OUT_FEAT];              // g = h @ W^T   (4 MB)
__device__ float  SIAg[N_NODES * N_HEADS];                // exp(s_i)
__device__ float  SIBg[N_NODES * N_HEADS];                // exp(0.2*s_i)
__device__ float2 SJ2g[N_NODES * N_HEADS];                // (exp(s_j), exp(0.2*s_j))
__device__ float  num_part[NSPLIT][N_NODES * OUT_FEAT];   // 64 MB partial numerators
__device__ float  den_part[NSPLIT][N_NODES * N_HEADS];    // partial denominators

// ---------------- K0: no-op spacer so ncu (4th launch) captures attn -----
__global__ void spacer_kernel() {}

// ---------------- cp.async helpers ----------------
__device__ __forceinline__ void cp_async16(void* sdst, const void* gsrc) {
    unsigned s = (unsigned)__cvta_generic_to_shared(sdst);
    asm volatile("cp.async.cg.shared.global [%0], [%1], 16;" :: "r"(s), "l"(gsrc));
}
__device__ __forceinline__ void cp_async8(void* sdst, const void* gsrc) {
    unsigned s = (unsigned)__cvta_generic_to_shared(sdst);
    asm volatile("cp.async.ca.shared.global [%0], [%1], 8;" :: "r"(s), "l"(gsrc));
}
__device__ __forceinline__ void cp_commit() { asm volatile("cp.async.commit_group;"); }
__device__ __forceinline__ void cp_wait_all() { asm volatile("cp.async.wait_group 0;" ::: "memory"); }

// ---------------- K1: g = h @ W^T  (both row-major, K contiguous) --------
__global__ __launch_bounds__(256) void gemm_g_kernel(const float* __restrict__ A,
                                                     const float* __restrict__ W) {
    __shared__ float As[16][68];
    __shared__ float Bs[16][68];
    const int tid = threadIdx.x;
    const int n0 = blockIdx.x * 64;
    const int m0 = blockIdx.y * 64;
    const int tx = tid & 15, ty = tid >> 4;

    float c[4][4];
#pragma unroll
    for (int i = 0; i < 4; i++)
#pragma unroll
        for (int j = 0; j < 4; j++) c[i][j] = 0.f;

    const int r  = tid >> 2;
    const int kq = (tid & 3) << 2;

    for (int k0 = 0; k0 < IN_FEAT; k0 += 16) {
        float4 av = *(const float4*)(A + (n0 + r) * IN_FEAT + k0 + kq);
        float4 bv = *(const float4*)(W + (m0 + r) * IN_FEAT + k0 + kq);
        As[kq + 0][r] = av.x; As[kq + 1][r] = av.y; As[kq + 2][r] = av.z; As[kq + 3][r] = av.w;
        Bs[kq + 0][r] = bv.x; Bs[kq + 1][r] = bv.y; Bs[kq + 2][r] = bv.z; Bs[kq + 3][r] = bv.w;
        __syncthreads();
#pragma unroll
        for (int k = 0; k < 16; k++) {
            float4 a4 = *(const float4*)&As[k][ty * 4];
            float4 b4 = *(const float4*)&Bs[k][tx * 4];
            float aa[4] = {a4.x, a4.y, a4.z, a4.w};
            float bb[4] = {b4.x, b4.y, b4.z, b4.w};
#pragma unroll
            for (int i = 0; i < 4; i++)
#pragma unroll
                for (int j = 0; j < 4; j++) c[i][j] = fmaf(aa[i], bb[j], c[i][j]);
        }
        __syncthreads();
    }
#pragma unroll
    for (int i = 0; i < 4; i++) {
        float4 o = make_float4(c[i][0], c[i][1], c[i][2], c[i][3]);
        *(float4*)(g_buf + (n0 + ty * 4 + i) * OUT_FEAT + m0 + tx * 4) = o;
    }
}

// ---------------- K2: per-node scores + factored exps --------------------
__global__ __launch_bounds__(256) void s_kernel(const float* __restrict__ a) {
    __shared__ float a_s[64];
    const int tid = threadIdx.x;
    if (tid < 64) a_s[tid] = a[tid];
    __syncthreads();
    const int idx = blockIdx.x * 256 + tid;   // (n, h) pair
    const int n = idx >> 3, h = idx & 7;
    const float* grow = g_buf + n * OUT_FEAT + h * N_HIDDEN;
    float si = 0.f, sj = 0.f;
#pragma unroll
    for (int f = 0; f < N_HIDDEN; f++) {
        float gv = grow[f];
        si = fmaf(gv, a_s[f], si);
        sj = fmaf(gv, a_s[32 + f], sj);
    }
    SIAg[idx] = expf(si);
    SIBg[idx] = expf(0.2f * si);
    SJ2g[idx] = make_float2(expf(sj), expf(0.2f * sj));
}

// ---------------- K3: fused masked-softmax attention (split-j partials) --
// grid (128 i-blocks, 16 j-splits) = 2048 CTAs, 256 threads, 3 CTAs/SM.
// Inline weight compute (no w_s roundtrip): warp = head; lane -> (iq, fo).
// w = max(e^si*e^sj, e^.2si*e^.2sj) masked by adjacency bitmasks.
// g tile double-buffered via cp.async; ONE barrier per tile.
//
// smem layout (dynamic, 70656 B):
//   g_s  [2][32jj][256f] f32  @ 0      (64 KB)
//   sj_s [2][32jj][8h] float2 @ 65536  (4 KB)
//   bm_s [8t][32i] u32        @ 69632  (1 KB)
#define SMEM_ATTN 70656

__global__ __launch_bounds__(256, 3) void attn_kernel(const int* __restrict__ adj) {
    extern __shared__ unsigned char smem[];
    float*        g_s  = (float*)(smem);
    float2*       sj_s = (float2*)(smem + 65536);
    unsigned int* bm_s = (unsigned int*)(smem + 69632);

    const int tid   = threadIdx.x;
    const int i0    = blockIdx.x * 32;
    const int split = blockIdx.y;
    const int jbase = split * J_PER_SPLIT;

    const int h    = tid >> 5;      // warp == head
    const int lane = tid & 31;
    const int iq   = lane >> 2;     // 0..7 : i = iq*4 .. iq*4+3
    const int fo   = lane & 3;      // 0..3 : f = fo*8 .. fo*8+7

    // per-thread i scores (4 rows)
    float siA[4], siB[4];
#pragma unroll
    for (int il = 0; il < 4; il++) {
        siA[il] = SIAg[(i0 + iq * 4 + il) * 8 + h];
        siB[il] = SIBg[(i0 + iq * 4 + il) * 8 + h];
    }

    unsigned long long acc[16];     // acc[il*4+p]: i=iq*4+il, f-pair p
#pragma unroll
    for (int q = 0; q < 16; q++) acc[q] = 0ull;
    float den[4] = {0.f, 0.f, 0.f, 0.f};

    const int NT = J_PER_SPLIT / 32;   // 8 tiles

    // ---- build adjacency bitmasks for all 8 tiles up front ----
    {
        const int adj_r = tid >> 3, adj_q = tid & 7;
        const unsigned int red_mask = 0xFFu << (lane & 24);
        const long long row_off = (long long)(i0 + adj_r) * N_NODES + jbase;
#pragma unroll
        for (int t = 0; t < NT; t++) {
            int4 av = *(const int4*)(adj + row_off + t * 32 + adj_q * 4);
            unsigned int nib = (av.x != 0 ? 1u : 0u) | (av.y != 0 ? 2u : 0u) |
                               (av.z != 0 ? 4u : 0u) | (av.w != 0 ? 8u : 0u);
            unsigned int m = __reduce_or_sync(red_mask, nib << (adj_q * 4));
            if (adj_q == 0) bm_s[t * 32 + adj_r] = m;
        }
    }

    // ---- issue tile 0 copies ----
    {
        const float* gsrc = g_buf + jbase * OUT_FEAT;
#pragma unroll
        for (int q = 0; q < 8; q++)
            cp_async16(g_s + tid * 4 + q * 1024, gsrc + tid * 4 + q * 1024);
        cp_async8(sj_s + tid, SJ2g + jbase * 8 + tid);
        cp_commit();
    }

    for (int t = 0; t < NT; t++) {
        const int buf = t & 1;
        cp_wait_all();
        __syncthreads();                       // tile t visible; prev buf free

        if (t + 1 < NT) {                      // stage t+1 into other buffer
            const int nb = (t + 1) & 1;
            const float* gsrc = g_buf + (jbase + (t + 1) * 32) * OUT_FEAT;
#pragma unroll
            for (int q = 0; q < 8; q++)
                cp_async16(g_s + nb * 8192 + tid * 4 + q * 1024, gsrc + tid * 4 + q * 1024);
            cp_async8(sj_s + nb * 256 + tid, SJ2g + (jbase + (t + 1) * 32) * 8 + tid);
            cp_commit();
        }

        // adjacency bits for this tile, 4 i-rows
        uint4 bmv = *(const uint4*)(bm_s + t * 32 + iq * 4);
        unsigned int bm[4] = {bmv.x, bmv.y, bmv.z, bmv.w};

        const float*      gb  = g_s + buf * 8192;
        const float2*     sjb = sj_s + buf * 256;

#pragma unroll 4
        for (int jj = 0; jj < 32; jj++) {
            // g values f = fo*8 .. fo*8+7 (two 16B loads, bank-disjoint)
            const ulonglong2* grow2 = (const ulonglong2*)gb + jj * 64 + h * 8 + fo * 2;
            ulonglong2 gp0 = grow2[0];
            ulonglong2 gp1 = grow2[1];
            float2 sj = sjb[jj * 8 + h];       // broadcast 8B

            unsigned long long wd[4];
#pragma unroll
            for (int il = 0; il < 4; il++) {
                float wA = siA[il] * sj.x;
                float wB = siB[il] * sj.y;
                float w  = fmaxf(wA, wB);                    // exp(leaky_relu)
                w = (bm[il] & (1u << jj)) ? w : 0.f;         // mask
                den[il] += w;
                asm("mov.b64 %0, {%1, %1};" : "=l"(wd[il]) : "f"(w));
            }
#pragma unroll
            for (int il = 0; il < 4; il++) {
                asm("fma.rn.f32x2 %0, %1, %2, %0;" : "+l"(acc[il * 4 + 0]) : "l"(wd[il]), "l"(gp0.x));
                asm("fma.rn.f32x2 %0, %1, %2, %0;" : "+l"(acc[il * 4 + 1]) : "l"(wd[il]), "l"(gp0.y));
                asm("fma.rn.f32x2 %0, %1, %2, %0;" : "+l"(acc[il * 4 + 2]) : "l"(wd[il]), "l"(gp1.x));
                asm("fma.rn.f32x2 %0, %1, %2, %0;" : "+l"(acc[il * 4 + 3]) : "l"(wd[il]), "l"(gp1.y));
            }
        }
        // NOTE: no trailing barrier; next iteration's wait+sync protects buffers
    }

    // ---- write partials (den identical across fo lanes; fo==0 writes) ----
    if (fo == 0) {
#pragma unroll
        for (int il = 0; il < 4; il++)
            den_part[split][(i0 + iq * 4 + il) * N_HEADS + h] = den[il];
    }

    float* nump = num_part[split];
#pragma unroll
    for (int il = 0; il < 4; il++) {
        const int i = iq * 4 + il;
        ulonglong2 o0, o1;
        o0.x = acc[il * 4 + 0]; o0.y = acc[il * 4 + 1];
        o1.x = acc[il * 4 + 2]; o1.y = acc[il * 4 + 3];
        float* dst = nump + (long long)(i0 + i) * OUT_FEAT + h * 32 + fo * 8;
        *(ulonglong2*)(dst)     = o0;
        *(ulonglong2*)(dst + 4) = o1;
    }
}

// ---------------- K4: reduce splits + normalize --------------------------
__global__ __launch_bounds__(256) void reduce_kernel(float* __restrict__ out) {
    const int idx = blockIdx.x * 256 + threadIdx.x;   // one float4 of output
    const int i  = idx >> 6;
    const int c4 = (idx & 63) * 4;
    const int h  = c4 >> 5;
    float4 s = make_float4(0.f, 0.f, 0.f, 0.f);
    float  d = 0.f;
#pragma unroll
    for (int sp = 0; sp < NSPLIT; sp++) {
        float4 v = *(const float4*)(num_part[sp] + i * OUT_FEAT + c4);
        s.x += v.x; s.y += v.y; s.z += v.z; s.w += v.w;
        d += den_part[sp][i * N_HEADS + h];
    }
    float rd = 1.0f / d;
    s.x *= rd; s.y *= rd; s.z *= rd; s.w *= rd;
    *(float4*)(out + i * OUT_FEAT + c4) = s;
}

// ---------------- launch ----------------
extern "C" void kernel_launch(void* const* d_in, const int* in_sizes, int n_in,
                              void* d_out, int out_size) {
    const float* h = nullptr;
    const float* W = nullptr;
    const float* a = nullptr;
    const int*   adj = nullptr;
    for (int i = 0; i < n_in; i++) {
        switch (in_sizes[i]) {
            case N_NODES * IN_FEAT:    h   = (const float*)d_in[i]; break;
            case OUT_FEAT * IN_FEAT:   W   = (const float*)d_in[i]; break;
            case 2 * N_HIDDEN:         a   = (const float*)d_in[i]; break;
            default:                   adj = (const int*)d_in[i];   break;
        }
    }
    float* out = (float*)d_out;

    cudaFuncSetAttribute(attn_kernel, cudaFuncAttributeMaxDynamicSharedMemorySize, SMEM_ATTN);

    spacer_kernel<<<1, 32>>>();   // keeps attn at 4th launch for ncu capture
    gemm_g_kernel<<<dim3(N_NODES / 64, OUT_FEAT / 64), 256>>>(h, W);
    s_kernel<<<N_NODES * N_HEADS / 256, 256>>>(a);
    attn_kernel<<<dim3(N_NODES / 32, NSPLIT), 256, SMEM_ATTN>>>(adj);
    reduce_kernel<<<N_NODES * OUT_FEAT / 1024, 256>>>(out);
    (void)out_size;
}